// round 15
// baseline (speedup 1.0000x reference)
#include <cuda_runtime.h>
#include <cuda_bf16.h>
#include <cstdint>

// FWHT, N = 4096, fp32, Sylvester ordering.  H4096 = H64 (x) H64.
// One CTA (64 threads) per row; 64 regs/thread of data.
//   Load:   64x LDG.32 coalesced (overlapped across 20 warps/SM).
//   Pass 1: fwht64 over e[11:6] in registers.
//   Exchange: rotation swizzle (conflict-free scalar STS, LDS.128 reads).
//   Pass 2: fwht64 over e[5:0]; thread t now holds final y[t*64 .. t*64+63].
//   Tail:   linear STS.128 into own block (rotated order, conflict-free,
//           same-thread => no barrier), then one 16 KB cp.async.bulk store.
// LSU wavefronts/row: 128 + 128 + 128 + 128 = 512   (R9 was 768).

#define FWHT_N 4096

__device__ __forceinline__ uint32_t smem_u32(const void* p) {
    return (uint32_t)__cvta_generic_to_shared(p);
}

__device__ __forceinline__ void fwht64(float v[64]) {
#pragma unroll
    for (int h = 1; h < 64; h <<= 1) {
#pragma unroll
        for (int i = 0; i < 64; i++) {
            if ((i & h) == 0) {
                float a = v[i];
                float b = v[i + h];
                v[i]     = a + b;
                v[i + h] = a - b;
            }
        }
    }
}

__global__ __launch_bounds__(64, 10)
void HadamardTransform_68891275428167_kernel(const float* __restrict__ x,
                                             float* __restrict__ y) {
    __shared__ __align__(128) float s[FWHT_N];   // 16 KB

    const int t = threadIdx.x;                   // 0..63
    const size_t row_off = (size_t)blockIdx.x * FWHT_N;
    const float* __restrict__ xr = x + row_off;

    float v[64];

    // ---- Load: v[hi] = x[hi*64 + t]; coalesced, 1 wf per warp-instr. ----
#pragma unroll
    for (int hi = 0; hi < 64; hi++)
        v[hi] = __ldcs(xr + (hi << 6) + t);

    fwht64(v);   // bits 11:6

    // ---- Exchange write: s[hi*64 + ((t + 4*hi) & 63)], conflict-free. ----
#pragma unroll
    for (int hi = 0; hi < 64; hi++)
        s[(hi << 6) + ((t + (hi << 2)) & 63)] = v[hi];
    __syncthreads();

    // ---- Exchange read: thread t reads its own 256B block as LDS.128,
    //      quads rotated (q + t) & 15  ->  v[4q+j] = element (t, 4q+j). ----
    {
        const float4* sv = reinterpret_cast<const float4*>(s + (t << 6));
#pragma unroll
        for (int q = 0; q < 16; q++) {
            float4 f = sv[(q + t) & 15];
            v[4 * q + 0] = f.x;
            v[4 * q + 1] = f.y;
            v[4 * q + 2] = f.z;
            v[4 * q + 3] = f.w;
        }
    }

    fwht64(v);   // bits 5:0  -> thread t holds final y[t*64 + lo], lo=0..63

    // ---- Linear STS.128 into own block, rotated issue order (CF);
    //      same-thread RMW of the block just read => no barrier needed. ----
    {
        float4* sv = reinterpret_cast<float4*>(s + (t << 6));
#pragma unroll
        for (int q = 0; q < 16; q++) {
            const int qq = (q + t) & 15;
            sv[qq] = make_float4(v[4 * qq + 0], v[4 * qq + 1],
                                 v[4 * qq + 2], v[4 * qq + 3]);
        }
    }
    __syncthreads();   // buffer complete before bulk store

    // ---- One 16 KB bulk store: smem (final layout) -> y[row]. ----
    if (t == 0) {
        asm volatile("fence.proxy.async.shared::cta;" ::: "memory");
        float* gdst = y + row_off;
        uint32_t ssrc = smem_u32(s);
        asm volatile("cp.async.bulk.global.shared::cta.bulk_group "
                     "[%0], [%1], %2;"
                     :: "l"(gdst), "r"(ssrc), "r"((uint32_t)(FWHT_N * 4))
                     : "memory");
        asm volatile("cp.async.bulk.commit_group;" ::: "memory");
        // Drain before CTA retirement frees the smem the engine reads.
        asm volatile("cp.async.bulk.wait_group 0;" ::: "memory");
    }
}

extern "C" void kernel_launch(void* const* d_in, const int* in_sizes, int n_in,
                              void* d_out, int out_size) {
    const float* x = (const float*)d_in[0];
    float* y = (float*)d_out;

    const int rows = in_sizes[0] / FWHT_N;   // 16384
    HadamardTransform_68891275428167_kernel<<<rows, 64>>>(x, y);
}

// round 16
// speedup vs baseline: 1.5443x; 1.5443x over previous
#include <cuda_runtime.h>
#include <cuda_bf16.h>
#include <cstdint>

// FWHT, N = 4096, fp32, Sylvester ordering.
// Element e[11:0]; thread t (64/CTA) ; regs r = 4j+c -> e = j*256 + t*4 + c,
// i.e. regs carry bits {11:8, 1:0}, thread carries bits {7:2}.
//   1. 16x LDG.128 coalesced.
//   2. 16x STS.128, float4-rotation swizzle  s4[j*64 + ((t+j)&63)]  (CF).
//   3. scalar-LDS transpose read -> fwht64 over bits 7:2 -> scalar STS back
//      to the SAME addresses (same-thread swap => no barrier, CF banks).
//   4. 16x LDS.128 (same rotation) -> fwht64 over bits {11:8,1:0}
//      -> 16x STG.128 straight from registers, coalesced.
// Wavefronts/row: 6*128 = 768 (same as best); mem instrs 288 -> 192,
// LDG front-batch 64 -> 16, barriers = 2.

#define FWHT_N 4096

__device__ __forceinline__ void fwht64(float v[64]) {
#pragma unroll
    for (int h = 1; h < 64; h <<= 1) {
#pragma unroll
        for (int i = 0; i < 64; i++) {
            if ((i & h) == 0) {
                float a = v[i];
                float b = v[i + h];
                v[i]     = a + b;
                v[i + h] = a - b;
            }
        }
    }
}

__global__ __launch_bounds__(64, 10)
void HadamardTransform_68891275428167_kernel(const float* __restrict__ x,
                                             float* __restrict__ y) {
    __shared__ __align__(16) float s[FWHT_N];   // 16 KB
    float4* s4 = reinterpret_cast<float4*>(s);

    const int t = threadIdx.x;                   // 0..63  (= e[7:2] role)
    const size_t row_off = (size_t)blockIdx.x * FWHT_N;
    const float4* __restrict__ x4 =
        reinterpret_cast<const float4*>(x + row_off);
    float4* __restrict__ y4 = reinterpret_cast<float4*>(y + row_off);

    float v[64];

    // ---- 1. Load: float4 j at x4[j*64 + t]  ->  v[4j+c] = e(j,t,c). ----
#pragma unroll
    for (int j = 0; j < 16; j++) {
        float4 f = __ldcs(x4 + (j << 6) + t);
        v[4 * j + 0] = f.x;
        v[4 * j + 1] = f.y;
        v[4 * j + 2] = f.z;
        v[4 * j + 3] = f.w;
    }

    // ---- 2. Transpose-in: STS.128 rotated; quad (j, (t+j)&63). CF. ----
#pragma unroll
    for (int j = 0; j < 16; j++)
        s4[(j << 6) + ((t + j) & 63)] =
            make_float4(v[4 * j + 0], v[4 * j + 1],
                        v[4 * j + 2], v[4 * j + 3]);
    __syncthreads();

    // ---- 3. Thread t = (jj,cc) gathers all m (old thread bits). CF. ----
    const int jj = t >> 2;
    const int cc = t & 3;
    {
        const float* base = s + jj * 256 + cc;
#pragma unroll
        for (int m = 0; m < 64; m++)
            v[m] = base[((m + jj) & 63) << 2];
    }

    fwht64(v);   // bits 7:2

    // ---- Write back to the SAME addresses (own set; no barrier). ----
    {
        float* base = s + jj * 256 + cc;
#pragma unroll
        for (int m = 0; m < 64; m++)
            base[((m + jj) & 63) << 2] = v[m];
    }
    __syncthreads();

    // ---- 4. Transpose-out: LDS.128 rotated; quad (j, (t+j)&63). CF. ----
#pragma unroll
    for (int j = 0; j < 16; j++) {
        float4 f = s4[(j << 6) + ((t + j) & 63)];
        v[4 * j + 0] = f.x;
        v[4 * j + 1] = f.y;
        v[4 * j + 2] = f.z;
        v[4 * j + 3] = f.w;
    }

    fwht64(v);   // bits {11:8, 1:0}

    // ---- Store: STG.128 coalesced straight from registers. ----
#pragma unroll
    for (int j = 0; j < 16; j++)
        __stcs(y4 + (j << 6) + t,
               make_float4(v[4 * j + 0], v[4 * j + 1],
                           v[4 * j + 2], v[4 * j + 3]));
}

extern "C" void kernel_launch(void* const* d_in, const int* in_sizes, int n_in,
                              void* d_out, int out_size) {
    const float* x = (const float*)d_in[0];
    float* y = (float*)d_out;

    const int rows = in_sizes[0] / FWHT_N;   // 16384
    HadamardTransform_68891275428167_kernel<<<rows, 64>>>(x, y);
}